// round 8
// baseline (speedup 1.0000x reference)
#include <cuda_runtime.h>
#include <cuda_bf16.h>

// ---------------------------------------------------------------------------
// EMD loss (multiplicative Sinkhorn, 2*eps == 1), full tensor-core core.
//   C = row-minmax-norm(1 - cos(x1[i],x2[i]))   [tf32 mma.m16n8k8]
//   E = exp(-2C);  eu0 = q1/rowsum(E);
//   {ev = q2/(eu@E) ; eu = q1/(ev@E^T)} x4 ; ev = q2/(eu@E)   [bf16 HMMA]
//   loss += eu^T (E.*C) ev                                     [bf16 HMMA]
// 128 blocks x 512 threads. Sinkhorn phases sync only within 4-warp row
// groups (named barriers) -- both phase GEMMs have `a` as the row dim, so
// warp (rb,cb)'s next A-operand rows come from its own rb-group.
// ---------------------------------------------------------------------------

#define SMEM_BYTES 117888

#define OB_X1    0        // f32(tf32) x1 [j][h] stride 68  (17408)
#define OB_X2    17408    // f32(tf32) x2 [k][h] stride 68  (17408)
#define OB_C     34816    // f32 C [j][k] stride 68         (17408)
#define OB_Q1B   52224    // bf16 q1 [a][j] stride 72       (9216)
#define OB_Q2B   61440    // bf16 q2 [a][k]                 (9216)
#define OB_EB    70656    // bf16 E  [j][k]                 (9216)
#define OB_ETB   79872    // bf16 E^T [k][j] stride 74      (9472)
#define OB_GB    89344    // bf16 E.*C [j][k]               (9216)
#define OB_EUB   98560    // bf16 eu [a][j]                 (9216)
#define OB_EVB   107776   // bf16 ev [a][k]                 (9216)
#define OB_I1    116992
#define OB_I2    117248
#define OB_RS    117504
#define OB_RED   117760
#define OB_FLAG  117824

#define STF 68            // fp32 row stride (words)
#define STW 36            // bf16 row stride in 32-bit words
#define STTW 37           // ET row stride in words

__device__ float g_partials[128];
__device__ unsigned int g_count = 0;

__device__ __forceinline__ float tf32r(float x) {
    float r; asm("cvt.rna.tf32.f32 %0, %1;" : "=f"(r) : "f"(x)); return r;
}

__device__ __forceinline__ void mma_bf16(float c[4], unsigned a0, unsigned a1,
                                         unsigned a2, unsigned a3,
                                         unsigned b0, unsigned b1)
{
    asm volatile(
        "mma.sync.aligned.m16n8k16.row.col.f32.bf16.bf16.f32 "
        "{%0,%1,%2,%3}, {%4,%5,%6,%7}, {%8,%9}, {%0,%1,%2,%3};"
        : "+f"(c[0]), "+f"(c[1]), "+f"(c[2]), "+f"(c[3])
        : "r"(a0), "r"(a1), "r"(a2), "r"(a3), "r"(b0), "r"(b1));
}

__device__ __forceinline__ void mma_tf32(float c[4], float a0, float a1,
                                         float a2, float a3, float b0, float b1)
{
    asm volatile(
        "mma.sync.aligned.m16n8k8.row.col.f32.tf32.tf32.f32 "
        "{%0,%1,%2,%3}, {%4,%5,%6,%7}, {%8,%9}, {%0,%1,%2,%3};"
        : "+f"(c[0]), "+f"(c[1]), "+f"(c[2]), "+f"(c[3])
        : "f"(a0), "f"(a1), "f"(a2), "f"(a3), "f"(b0), "f"(b1));
}

__device__ __forceinline__ float2 unpack_bf2(unsigned w) {
    __nv_bfloat162 h = *reinterpret_cast<__nv_bfloat162*>(&w);
    return __bfloat1622float2(h);
}
__device__ __forceinline__ unsigned pack_bf2(float lo, float hi) {
    __nv_bfloat162 h = __floats2bfloat162_rn(lo, hi);
    return *reinterpret_cast<unsigned*>(&h);
}

// One 64x64x64 bf16 GEMM phase + fp32 epilogue division.
// out[r][c] = sum_k A[r][k] * Bt[c][k];  Dst = Q / out (bf16).
__device__ __forceinline__ void mma_div_phase(
    const unsigned* __restrict__ A32, const unsigned* __restrict__ B32,
    int bstw, const unsigned* __restrict__ Q32, unsigned* __restrict__ D32,
    int wid, int lane)
{
    const int rb = wid & 3, cb = wid >> 2;
    const int g = lane >> 2, tg = lane & 3;
    const int r0 = rb * 16;
    float acc[2][4] = {};
    const int abase = (r0 + g) * STW + tg;
#pragma unroll
    for (int kc = 0; kc < 4; kc++) {
        unsigned a0 = A32[abase + 8 * kc];
        unsigned a1 = A32[abase + 8 * STW + 8 * kc];
        unsigned a2 = A32[abase + 8 * kc + 4];
        unsigned a3 = A32[abase + 8 * STW + 8 * kc + 4];
#pragma unroll
        for (int t = 0; t < 2; t++) {
            int bbase = (cb * 16 + 8 * t + g) * bstw + tg;
            unsigned b0 = B32[bbase + 8 * kc];
            unsigned b1 = B32[bbase + 8 * kc + 4];
            mma_bf16(acc[t], a0, a1, a2, a3, b0, b1);
        }
    }
#pragma unroll
    for (int t = 0; t < 2; t++) {
        int colw = cb * 8 + 4 * t + tg;
        int rlo = r0 + g, rhi = rlo + 8;
        float2 ql = unpack_bf2(Q32[rlo * STW + colw]);
        float2 qh = unpack_bf2(Q32[rhi * STW + colw]);
        D32[rlo * STW + colw] = pack_bf2(__fdividef(ql.x, acc[t][0]),
                                         __fdividef(ql.y, acc[t][1]));
        D32[rhi * STW + colw] = pack_bf2(__fdividef(qh.x, acc[t][2]),
                                         __fdividef(qh.y, acc[t][3]));
    }
}

__global__ __launch_bounds__(512, 1)
void emd_main(const float* __restrict__ f10, const float* __restrict__ f11,
              const float* __restrict__ f20, const float* __restrict__ f21,
              float* __restrict__ out)
{
    extern __shared__ char smb[];
    const int blk  = blockIdx.x;
    const int pair = blk >> 6;
    const int i    = blk & 63;
    const float* __restrict__ X1g = pair ? f11 : f10;
    const float* __restrict__ X2g = pair ? f21 : f20;

    const int tid  = threadIdx.x;
    const int lane = tid & 31;
    const int wid  = tid >> 5;        // 0..15
    const int rbid = (wid & 3) + 1;   // named barrier id for this row group

    float* sX1 = (float*)(smb + OB_X1);
    float* sX2 = (float*)(smb + OB_X2);
    float* sC  = (float*)(smb + OB_C);
    float* sI1 = (float*)(smb + OB_I1);
    float* sI2 = (float*)(smb + OB_I2);
    float* sRS = (float*)(smb + OB_RS);
    float* sRed = (float*)(smb + OB_RED);
    int*   sFlag = (int*)(smb + OB_FLAG);
    __nv_bfloat16* sQ1b = (__nv_bfloat16*)(smb + OB_Q1B);
    __nv_bfloat16* sQ2b = (__nv_bfloat16*)(smb + OB_Q2B);
    __nv_bfloat16* sEb  = (__nv_bfloat16*)(smb + OB_EB);
    __nv_bfloat16* sETb = (__nv_bfloat16*)(smb + OB_ETB);
    __nv_bfloat16* sGb  = (__nv_bfloat16*)(smb + OB_GB);
    unsigned* Q1_32 = (unsigned*)(smb + OB_Q1B);
    unsigned* Q2_32 = (unsigned*)(smb + OB_Q2B);
    unsigned* E_32  = (unsigned*)(smb + OB_EB);
    unsigned* ET_32 = (unsigned*)(smb + OB_ETB);
    unsigned* G_32  = (unsigned*)(smb + OB_GB);
    unsigned* EU_32 = (unsigned*)(smb + OB_EUB);
    unsigned* EV_32 = (unsigned*)(smb + OB_EVB);

    // ---- load tiles (tf32-prerounded, stride 68); inverse norms inline ----
    {
        const float4* g1 = (const float4*)(X1g + i * 4096);
        const float4* g2 = (const float4*)(X2g + i * 4096);
#pragma unroll
        for (int m = 0; m < 2; m++) {
            int v = tid + m * 512;
            int r = v >> 4;
            int c = (v & 15) << 2;
            float4 a = g1[v];
            float4 b = g2[v];
            float4 ar; ar.x = tf32r(a.x); ar.y = tf32r(a.y);
                       ar.z = tf32r(a.z); ar.w = tf32r(a.w);
            float4 br; br.x = tf32r(b.x); br.y = tf32r(b.y);
                       br.z = tf32r(b.z); br.w = tf32r(b.w);
            *(float4*)(sX1 + r * STF + c) = ar;
            *(float4*)(sX2 + r * STF + c) = br;
            float s1 = a.x * a.x + a.y * a.y + a.z * a.z + a.w * a.w;
            float s2 = b.x * b.x + b.y * b.y + b.z * b.z + b.w * b.w;
#pragma unroll
            for (int o = 8; o; o >>= 1) {
                s1 += __shfl_xor_sync(~0u, s1, o);
                s2 += __shfl_xor_sync(~0u, s2, o);
            }
            if ((tid & 15) == 0) {
                sI1[r] = 1.0f / fmaxf(sqrtf(s1), 1e-8f);
                sI2[r] = 1.0f / fmaxf(sqrtf(s2), 1e-8f);
            }
        }
    }

    // ---- softmax -> q (bf16). No max-subtract: inputs are N(0,1), exp is
    //      safe in fp32; softmax(x) == exp(x)/sum(exp(x)) exactly. ----
    {
        float v1a[4], v1b[4], v2a[4], v2b[4];
#pragma unroll
        for (int r4 = 0; r4 < 4; r4++) {
            int a = wid * 4 + r4;
            const float* r1 = X1g + (a * 64 + i) * 64;
            const float* r2 = X2g + (a * 64 + i) * 64;
            v1a[r4] = r1[lane]; v1b[r4] = r1[lane + 32];
            v2a[r4] = r2[lane]; v2b[r4] = r2[lane + 32];
        }
#pragma unroll
        for (int r4 = 0; r4 < 4; r4++) {
            int a = wid * 4 + r4;
            float e1a = __expf(v1a[r4]), e1b = __expf(v1b[r4]);
            float e2a = __expf(v2a[r4]), e2b = __expf(v2b[r4]);
            float s1 = e1a + e1b;
            float s2 = e2a + e2b;
#pragma unroll
            for (int o = 16; o; o >>= 1) {
                s1 += __shfl_xor_sync(~0u, s1, o);
                s2 += __shfl_xor_sync(~0u, s2, o);
            }
            float i1 = __fdividef(1.0f, s1);
            float i2 = __fdividef(1.0f, s2);
            sQ1b[a * 72 + lane]      = __float2bfloat16(e1a * i1 + 1e-12f);
            sQ1b[a * 72 + lane + 32] = __float2bfloat16(e1b * i1 + 1e-12f);
            sQ2b[a * 72 + lane]      = __float2bfloat16(e2a * i2 + 1e-12f);
            sQ2b[a * 72 + lane + 32] = __float2bfloat16(e2b * i2 + 1e-12f);
        }
    }
    __syncthreads();

    // ---- C = 1 - cosine via tf32 mma (A = x1 rows, Bt = x2 rows) ----
    {
        const int rb = wid & 3, cb = wid >> 2;
        const int g = lane >> 2, tg = lane & 3;
        const int r0 = rb * 16;
        float acc[2][4] = {};
        const int abase = (r0 + g) * STF + tg;
#pragma unroll
        for (int kc = 0; kc < 8; kc++) {
            float a0 = sX1[abase + 8 * kc];
            float a1 = sX1[abase + 8 * STF + 8 * kc];
            float a2 = sX1[abase + 8 * kc + 4];
            float a3 = sX1[abase + 8 * STF + 8 * kc + 4];
#pragma unroll
            for (int t = 0; t < 2; t++) {
                int bbase = (cb * 16 + 8 * t + g) * STF + tg;
                float b0 = sX2[bbase + 8 * kc];
                float b1 = sX2[bbase + 8 * kc + 4];
                mma_tf32(acc[t], a0, a1, a2, a3, b0, b1);
            }
        }
        int rlo = r0 + g, rhi = rlo + 8;
        float i1lo = sI1[rlo], i1hi = sI1[rhi];
#pragma unroll
        for (int t = 0; t < 2; t++) {
            int col = cb * 16 + 8 * t + 2 * tg;
            float i2a = sI2[col], i2b = sI2[col + 1];
            float2 lo, hi;
            lo.x = 1.0f - acc[t][0] * i1lo * i2a;
            lo.y = 1.0f - acc[t][1] * i1lo * i2b;
            hi.x = 1.0f - acc[t][2] * i1hi * i2a;
            hi.y = 1.0f - acc[t][3] * i1hi * i2b;
            *(float2*)(sC + rlo * STF + col) = lo;
            *(float2*)(sC + rhi * STF + col) = hi;
        }
    }
    __syncthreads();

    // ---- fused: per-row minmax -> normalize -> E, E^T, G, 1/rowsum ----
#pragma unroll 1
    for (int r4 = 0; r4 < 4; r4++) {
        int j = wid * 4 + r4;
        float c0v = sC[j * STF + lane];
        float c1v = sC[j * STF + 32 + lane];
        float mn = fminf(c0v, c1v), mx = fmaxf(c0v, c1v);
#pragma unroll
        for (int o = 16; o; o >>= 1) {
            mn = fminf(mn, __shfl_xor_sync(~0u, mn, o));
            mx = fmaxf(mx, __shfl_xor_sync(~0u, mx, o));
        }
        float rinv = 1.0f / (mx - mn);
        float cn0 = (c0v - mn) * rinv;
        float cn1 = (c1v - mn) * rinv;
        float e0 = __expf(-2.0f * cn0);
        float e1 = __expf(-2.0f * cn1);
        sEb[j * 72 + lane]      = __float2bfloat16(e0);
        sEb[j * 72 + lane + 32] = __float2bfloat16(e1);
        sGb[j * 72 + lane]      = __float2bfloat16(e0 * cn0);
        sGb[j * 72 + lane + 32] = __float2bfloat16(e1 * cn1);
        sETb[lane * 74 + j]        = __float2bfloat16(e0);
        sETb[(lane + 32) * 74 + j] = __float2bfloat16(e1);
        float s = e0 + e1;
#pragma unroll
        for (int o = 16; o; o >>= 1) s += __shfl_xor_sync(~0u, s, o);
        if (lane == 0) sRS[j] = __fdividef(1.0f, s);
    }
    __syncthreads();

    // ---- EU0 = q1 * (1/rowsumE) ----
    {
        int a = tid >> 3, j0 = (tid & 7) * 8;
#pragma unroll
        for (int p = 0; p < 4; p++) {
            float2 q = unpack_bf2(Q1_32[a * STW + (j0 >> 1) + p]);
            EU_32[a * STW + (j0 >> 1) + p] =
                pack_bf2(q.x * sRS[j0 + 2 * p], q.y * sRS[j0 + 2 * p + 1]);
        }
    }
    __syncthreads();

    // ---- Sinkhorn: 5 v-phases, 4 u-phases; row-group named barriers only.
    //      Both phases have `a` as rows, so warp (rb,cb)'s next A rows are
    //      produced by its own rb-group (warps rb, rb+4, rb+8, rb+12). ----
#pragma unroll 1
    for (int it = 0; it < 5; it++) {
        // v: T[a][k] = sum_j EU[a][j] * ET[k][j];  EV = Q2 / T
        mma_div_phase(EU_32, ET_32, STTW, Q2_32, EV_32, wid, lane);
        asm volatile("bar.sync %0, 128;" :: "r"(rbid) : "memory");
        if (it == 4) break;
        // u: S[a][j] = sum_k EV[a][k] * E[j][k];  EU = Q1 / S
        mma_div_phase(EV_32, E_32, STW, Q1_32, EU_32, wid, lane);
        asm volatile("bar.sync %0, 128;" :: "r"(rbid) : "memory");
    }

    // ---- final: T2 = EV @ G^T;  loss = sum EU .* T2 ----
    float local = 0.0f;
    {
        const int rb = wid & 3, cb = wid >> 2;
        const int g = lane >> 2, tg = lane & 3;
        const int r0 = rb * 16;
        float acc[2][4] = {};
        const int abase = (r0 + g) * STW + tg;
#pragma unroll
        for (int kc = 0; kc < 4; kc++) {
            unsigned a0_ = EV_32[abase + 8 * kc];
            unsigned a1_ = EV_32[abase + 8 * STW + 8 * kc];
            unsigned a2_ = EV_32[abase + 8 * kc + 4];
            unsigned a3_ = EV_32[abase + 8 * STW + 8 * kc + 4];
#pragma unroll
            for (int tt = 0; tt < 2; tt++) {
                int bbase = (cb * 16 + 8 * tt + g) * STW + tg;
                mma_bf16(acc[tt], a0_, a1_, a2_, a3_,
                         G_32[bbase + 8 * kc], G_32[bbase + 8 * kc + 4]);
            }
        }
#pragma unroll
        for (int tt = 0; tt < 2; tt++) {
            int colw = cb * 8 + 4 * tt + tg;
            int rlo = r0 + g, rhi = rlo + 8;
            float2 el = unpack_bf2(EU_32[rlo * STW + colw]);
            float2 eh = unpack_bf2(EU_32[rhi * STW + colw]);
            local += el.x * acc[tt][0] + el.y * acc[tt][1]
                   + eh.x * acc[tt][2] + eh.y * acc[tt][3];
        }
    }
#pragma unroll
    for (int o = 16; o; o >>= 1) local += __shfl_xor_sync(~0u, local, o);
    if (lane == 0) sRed[wid] = local;
    __syncthreads();

    // ---- publish partial; last block reduces deterministically ----
    if (tid == 0) {
        float tt = 0.0f;
#pragma unroll
        for (int w = 0; w < 16; w++) tt += sRed[w];
        g_partials[blk] = tt;
        __threadfence();
        unsigned int old = atomicAdd(&g_count, 1u);
        sFlag[0] = (old == 127u);
    }
    __syncthreads();
    if (sFlag[0] && wid == 0) {
        __threadfence();
        float v = g_partials[lane] + g_partials[lane + 32]
                + g_partials[lane + 64] + g_partials[lane + 96];
#pragma unroll
        for (int o = 16; o; o >>= 1) v += __shfl_xor_sync(~0u, v, o);
        if (lane == 0) {
            out[0] = v * (1.0f / 8192.0f);
            g_count = 0;
        }
    }
}

extern "C" void kernel_launch(void* const* d_in, const int* in_sizes, int n_in,
                              void* d_out, int out_size)
{
    (void)in_sizes; (void)n_in; (void)out_size;
    cudaFuncSetAttribute(emd_main, cudaFuncAttributeMaxDynamicSharedMemorySize, SMEM_BYTES);
    emd_main<<<128, 512, SMEM_BYTES>>>((const float*)d_in[0], (const float*)d_in[1],
                                       (const float*)d_in[2], (const float*)d_in[3],
                                       (float*)d_out);
}